// round 1
// baseline (speedup 1.0000x reference)
#include <cuda_runtime.h>
#include <math.h>

#define BB    2
#define TT    2048
#define DD    2048
#define HH    16
#define DK    128
#define N3    (3*DD)
#define MROWS (BB*TT)   // 4096

// ---------------- scratch (device globals; no allocation allowed) ----------------
__device__ float g_kqv[(size_t)MROWS * N3];   // ~100 MB
__device__ float g_attn[(size_t)MROWS * DD];  // ~33 MB
__device__ float g_inv[64];
__device__ float g_cos[TT * 64];
__device__ float g_sin[TT * 64];

// ---------------- SGEMM: C[M,N] = A[M,K] @ W[K,N] + bias[N] ----------------
// 128x128 tile, BK=8, 256 threads, 8x8 per thread. All dims multiples of tile.
__global__ __launch_bounds__(256, 2)
void sgemm_bias_kernel(const float* __restrict__ A, const float* __restrict__ W,
                       const float* __restrict__ bias, float* __restrict__ C,
                       int M, int N, int K)
{
    __shared__ float As[8][128];   // transposed A tile: As[k][m]
    __shared__ float Bs[8][128];   // Bs[k][n]

    const int t  = threadIdx.x;
    const int tx = t & 15;
    const int ty = t >> 4;
    const int rowBase = blockIdx.y * 128;
    const int colBase = blockIdx.x * 128;

    const int arow = t >> 1;
    const int acol = (t & 1) * 4;
    const int brow = t >> 5;
    const int bcol = (t & 31) * 4;

    float acc[8][8];
    #pragma unroll
    for (int i = 0; i < 8; i++)
        #pragma unroll
        for (int j = 0; j < 8; j++) acc[i][j] = 0.0f;

    for (int k0 = 0; k0 < K; k0 += 8) {
        float4 av = *(const float4*)&A[(size_t)(rowBase + arow) * K + k0 + acol];
        float4 bv = *(const float4*)&W[(size_t)(k0 + brow) * N + colBase + bcol];
        As[acol + 0][arow] = av.x;
        As[acol + 1][arow] = av.y;
        As[acol + 2][arow] = av.z;
        As[acol + 3][arow] = av.w;
        *(float4*)&Bs[brow][bcol] = bv;
        __syncthreads();

        #pragma unroll
        for (int kk = 0; kk < 8; kk++) {
            float a[8], b[8];
            *(float4*)&a[0] = *(const float4*)&As[kk][ty * 8];
            *(float4*)&a[4] = *(const float4*)&As[kk][ty * 8 + 4];
            *(float4*)&b[0] = *(const float4*)&Bs[kk][tx * 8];
            *(float4*)&b[4] = *(const float4*)&Bs[kk][tx * 8 + 4];
            #pragma unroll
            for (int i = 0; i < 8; i++)
                #pragma unroll
                for (int j = 0; j < 8; j++)
                    acc[i][j] += a[i] * b[j];
        }
        __syncthreads();
    }

    #pragma unroll
    for (int i = 0; i < 8; i++) {
        const int r = rowBase + ty * 8 + i;
        #pragma unroll
        for (int j = 0; j < 8; j += 4) {
            const int c = colBase + tx * 8 + j;
            float4 o;
            o.x = acc[i][j + 0] + bias[c + 0];
            o.y = acc[i][j + 1] + bias[c + 1];
            o.z = acc[i][j + 2] + bias[c + 2];
            o.w = acc[i][j + 3] + bias[c + 3];
            *(float4*)&C[(size_t)r * N + c] = o;
        }
    }
}

// ---------------- RoPE tables ----------------
__global__ void freq_kernel(float* __restrict__ inv)
{
    int p = threadIdx.x;
    if (p < 64) inv[p] = (float)pow(10000.0, -(double)p / 64.0);
}

__global__ void trig_kernel(const float* __restrict__ inv,
                            float* __restrict__ ct, float* __restrict__ st)
{
    int idx = blockIdx.x * blockDim.x + threadIdx.x;
    if (idx >= TT * 64) return;
    int tpos = idx >> 6;
    int p    = idx & 63;
    float ang = (float)tpos * inv[p];
    float s, c;
    sincosf(ang, &s, &c);
    ct[idx] = c;
    st[idx] = s;
}

// ---------------- RoPE apply (k and q sections of g_kqv, in place) ----------------
__global__ void rope_kernel(float* __restrict__ kqv,
                            const float* __restrict__ ct, const float* __restrict__ st)
{
    int idx = blockIdx.x * blockDim.x + threadIdx.x;   // MROWS * DD pairs
    if (idx >= MROWS * DD) return;
    int row  = idx >> 11;          // / 2048
    int r    = idx & 2047;
    int sect = r >> 10;            // 0 = k, 1 = q
    int p    = r & 1023;           // pair index within section
    int h    = p >> 6;
    int pj   = p & 63;
    int tpos = row & (TT - 1);

    float c = ct[tpos * 64 + pj];
    float s = st[tpos * 64 + pj];

    size_t base = (size_t)row * N3 + (size_t)sect * DD + h * DK + 2 * pj;
    float2 v = *(float2*)&kqv[base];
    float2 o;
    o.x = v.x * c - v.y * s;
    o.y = v.x * s + v.y * c;
    *(float2*)&kqv[base] = o;
}

// ---------------- Flash attention (fp32, causal) ----------------
// Block: 128 queries x one (b,h). Key tiles of 64. 256 threads.
// S phase: thread = 8q x 4k.  O phase: thread = 8q x 8d (same ty -> same q rows).
#define LDQ 132
#define LDK 68
#define LDP 129
#define ATTN_SMEM_FLOATS (128*LDQ + 128*LDK + 64*128 + 64*LDP)
#define ATTN_SMEM_BYTES  (ATTN_SMEM_FLOATS * 4)

__global__ __launch_bounds__(256, 1)
void attn_kernel()
{
    extern __shared__ float sm[];
    float* Qs = sm;                     // [128 d][LDQ]  (q-index inner)
    float* Ks = Qs + 128 * LDQ;         // [128 d][LDK]  (k-index inner)
    float* Vs = Ks + 128 * LDK;         // [64 k][128 d]
    float* Ps = Vs + 64 * 128;          // [64 k][LDP]   (q-index inner)

    const int t  = threadIdx.x;
    const int tx = t & 15;
    const int ty = t >> 4;
    const int bh = blockIdx.y;
    const int b  = bh >> 4;
    const int h  = bh & 15;
    const int qt = (int)gridDim.x - 1 - (int)blockIdx.x;   // heavy tiles first
    const int qbase = qt * 128;
    const size_t rowbase = (size_t)b * TT;
    const float scale = 0.08838834764831845f;  // 1/sqrt(128)

    // ---- load Q tile transposed: Qs[d][qi] ----
    for (int u = t; u < 128 * 32; u += 256) {
        int qi = u & 127;
        int dg = u >> 7;      // 0..31 (float4 of dims)
        const float* src = g_kqv + (rowbase + qbase + qi) * N3 + DD + h * DK + dg * 4;
        float4 v = *(const float4*)src;
        Qs[(dg * 4 + 0) * LDQ + qi] = v.x;
        Qs[(dg * 4 + 1) * LDQ + qi] = v.y;
        Qs[(dg * 4 + 2) * LDQ + qi] = v.z;
        Qs[(dg * 4 + 3) * LDQ + qi] = v.w;
    }

    float o[8][8];
    #pragma unroll
    for (int i = 0; i < 8; i++)
        #pragma unroll
        for (int j = 0; j < 8; j++) o[i][j] = 0.0f;
    float m[8], l[8];
    #pragma unroll
    for (int i = 0; i < 8; i++) { m[i] = -1e30f; l[i] = 0.0f; }

    const int nkt = 2 * qt + 2;
    for (int kt = 0; kt < nkt; kt++) {
        const int kbase = kt * 64;
        __syncthreads();   // previous iteration's O phase done with Ks/Vs/Ps

        // ---- K tile transposed: Ks[d][ki] (lanes vary ki -> conflict-free stores) ----
        for (int u = t; u < 64 * 32; u += 256) {
            int ki = u & 63;
            int dg = u >> 6;
            const float* src = g_kqv + (rowbase + kbase + ki) * N3 + h * DK + dg * 4;
            float4 v = *(const float4*)src;
            Ks[(dg * 4 + 0) * LDK + ki] = v.x;
            Ks[(dg * 4 + 1) * LDK + ki] = v.y;
            Ks[(dg * 4 + 2) * LDK + ki] = v.z;
            Ks[(dg * 4 + 3) * LDK + ki] = v.w;
        }
        // ---- V tile: Vs[ki][d] (coalesced) ----
        for (int u = t; u < 64 * 32; u += 256) {
            int ki = u >> 5;
            int dg = u & 31;
            const float* src = g_kqv + (rowbase + kbase + ki) * N3 + 2 * DD + h * DK + dg * 4;
            *(float4*)&Vs[ki * 128 + dg * 4] = *(const float4*)src;
        }
        __syncthreads();

        // ---- S = Q @ K^T : s[8 q][4 k] ----
        float s[8][4];
        #pragma unroll
        for (int i = 0; i < 8; i++)
            #pragma unroll
            for (int j = 0; j < 4; j++) s[i][j] = 0.0f;

        #pragma unroll 2
        for (int d = 0; d < 128; d++) {
            float a[8], bv[4];
            *(float4*)&a[0]  = *(const float4*)&Qs[d * LDQ + ty * 8];
            *(float4*)&a[4]  = *(const float4*)&Qs[d * LDQ + ty * 8 + 4];
            *(float4*)&bv[0] = *(const float4*)&Ks[d * LDK + tx * 4];
            #pragma unroll
            for (int i = 0; i < 8; i++)
                #pragma unroll
                for (int j = 0; j < 4; j++)
                    s[i][j] += a[i] * bv[j];
        }

        // ---- scale + causal mask + online softmax ----
        #pragma unroll
        for (int i = 0; i < 8; i++) {
            const int qrow = qbase + ty * 8 + i;
            #pragma unroll
            for (int j = 0; j < 4; j++) {
                float v = s[i][j] * scale;
                if (kbase + tx * 4 + j > qrow) v = -1e30f;
                s[i][j] = v;
            }
            float rm = fmaxf(fmaxf(s[i][0], s[i][1]), fmaxf(s[i][2], s[i][3]));
            rm = fmaxf(rm, __shfl_xor_sync(0xffffffffu, rm, 1));
            rm = fmaxf(rm, __shfl_xor_sync(0xffffffffu, rm, 2));
            rm = fmaxf(rm, __shfl_xor_sync(0xffffffffu, rm, 4));
            rm = fmaxf(rm, __shfl_xor_sync(0xffffffffu, rm, 8));
            const float mnew = fmaxf(m[i], rm);
            const float f = __expf(m[i] - mnew);
            m[i] = mnew;

            float ps = 0.0f;
            #pragma unroll
            for (int j = 0; j < 4; j++) {
                float p = __expf(s[i][j] - mnew);
                s[i][j] = p;
                ps += p;
            }
            ps += __shfl_xor_sync(0xffffffffu, ps, 1);
            ps += __shfl_xor_sync(0xffffffffu, ps, 2);
            ps += __shfl_xor_sync(0xffffffffu, ps, 4);
            ps += __shfl_xor_sync(0xffffffffu, ps, 8);
            l[i] = l[i] * f + ps;

            #pragma unroll
            for (int j = 0; j < 8; j++) o[i][j] *= f;

            // store P transposed: Ps[k][q]
            #pragma unroll
            for (int j = 0; j < 4; j++)
                Ps[(tx * 4 + j) * LDP + ty * 8 + i] = s[i][j];
        }
        __syncthreads();

        // ---- O += P^T-as-[k][q] with V: o[8 q][8 d] ----
        #pragma unroll 2
        for (int k = 0; k < 64; k++) {
            float pv[8], vv[8];
            #pragma unroll
            for (int i = 0; i < 8; i++) pv[i] = Ps[k * LDP + ty * 8 + i];
            *(float4*)&vv[0] = *(const float4*)&Vs[k * 128 + tx * 8];
            *(float4*)&vv[4] = *(const float4*)&Vs[k * 128 + tx * 8 + 4];
            #pragma unroll
            for (int i = 0; i < 8; i++)
                #pragma unroll
                for (int j = 0; j < 8; j++)
                    o[i][j] += pv[i] * vv[j];
        }
    }

    // ---- epilogue: O / l -> g_attn[row][h*128 + d] ----
    #pragma unroll
    for (int i = 0; i < 8; i++) {
        const float invl = 1.0f / l[i];
        const size_t row = rowbase + qbase + ty * 8 + i;
        float* dst = g_attn + row * DD + h * DK + tx * 8;
        float4 o0, o1;
        o0.x = o[i][0] * invl; o0.y = o[i][1] * invl;
        o0.z = o[i][2] * invl; o0.w = o[i][3] * invl;
        o1.x = o[i][4] * invl; o1.y = o[i][5] * invl;
        o1.z = o[i][6] * invl; o1.w = o[i][7] * invl;
        *(float4*)&dst[0] = o0;
        *(float4*)&dst[4] = o1;
    }
}

// ---------------- launch ----------------
extern "C" void kernel_launch(void* const* d_in, const int* in_sizes, int n_in,
                              void* d_out, int out_size)
{
    const float* x    = (const float*)d_in[0];
    const float* Wkqv = (const float*)d_in[1];
    const float* bkqv = (const float*)d_in[2];
    const float* Wo   = (const float*)d_in[3];
    const float* bo   = (const float*)d_in[4];
    float* out = (float*)d_out;

    float *kqv, *attn, *inv, *ct, *st;
    cudaGetSymbolAddress((void**)&kqv,  g_kqv);
    cudaGetSymbolAddress((void**)&attn, g_attn);
    cudaGetSymbolAddress((void**)&inv,  g_inv);
    cudaGetSymbolAddress((void**)&ct,   g_cos);
    cudaGetSymbolAddress((void**)&st,   g_sin);

    cudaFuncSetAttribute(attn_kernel, cudaFuncAttributeMaxDynamicSharedMemorySize,
                         ATTN_SMEM_BYTES);

    // 1) kqv = x @ Wkqv + bkqv
    sgemm_bias_kernel<<<dim3(N3 / 128, MROWS / 128), 256>>>(x, Wkqv, bkqv, kqv,
                                                            MROWS, N3, DD);
    // 2) RoPE tables + apply to k,q
    freq_kernel<<<1, 64>>>(inv);
    trig_kernel<<<(TT * 64) / 256, 256>>>(inv, ct, st);
    rope_kernel<<<(MROWS * DD) / 256, 256>>>(kqv, ct, st);
    // 3) causal flash attention -> g_attn
    attn_kernel<<<dim3(TT / 128, BB * HH), 256, ATTN_SMEM_BYTES>>>();
    // 4) out = attn @ Wo + bo
    sgemm_bias_kernel<<<dim3(DD / 128, MROWS / 128), 256>>>(attn, Wo, bo, out,
                                                            MROWS, DD, DD);
}

// round 2
// speedup vs baseline: 1.8358x; 1.8358x over previous
#include <cuda_runtime.h>
#include <math.h>
#include <stdint.h>

#define BB    2
#define TT    2048
#define DD    2048
#define HH    16
#define DK    128
#define N3    (3*DD)
#define MROWS (BB*TT)   // 4096

// ---------------- scratch (device globals; no allocation allowed) ----------------
__device__ float g_kqv[(size_t)MROWS * N3];   // ~100 MB
__device__ float g_attn[(size_t)MROWS * DD];  // ~33 MB
__device__ float g_inv[64];
__device__ float g_cos[TT * 64];
__device__ float g_sin[TT * 64];

// ---------------- small PTX helpers ----------------
__device__ __forceinline__ uint32_t smem_u32(const void* p) {
    return (uint32_t)__cvta_generic_to_shared(p);
}
__device__ __forceinline__ void cp16(void* dst, const void* src) {
    asm volatile("cp.async.cg.shared.global [%0], [%1], 16;\n"
                 :: "r"(smem_u32(dst)), "l"(src));
}
__device__ __forceinline__ void cp_commit() {
    asm volatile("cp.async.commit_group;\n");
}
__device__ __forceinline__ void cp_wait0() {
    asm volatile("cp.async.wait_group 0;\n");
}
__device__ __forceinline__ uint32_t f2tf(float f) {
    uint32_t r;
    asm("cvt.rna.tf32.f32 %0, %1;" : "=r"(r) : "f"(f));
    return r;
}
__device__ __forceinline__ void mma_tf32(float c[4],
                                         uint32_t a0, uint32_t a1, uint32_t a2, uint32_t a3,
                                         uint32_t b0, uint32_t b1) {
    asm volatile(
        "mma.sync.aligned.m16n8k8.row.col.f32.tf32.tf32.f32 "
        "{%0,%1,%2,%3}, {%4,%5,%6,%7}, {%8,%9}, {%0,%1,%2,%3};\n"
        : "+f"(c[0]), "+f"(c[1]), "+f"(c[2]), "+f"(c[3])
        : "r"(a0), "r"(a1), "r"(a2), "r"(a3), "r"(b0), "r"(b1));
}

// ---------------- TF32 tensor-core GEMM: C[M,N] = A[M,K] @ W[K,N] + bias ----------------
// CTA tile 128x128, BK=16, 256 threads (8 warps, 2x4), warp tile 64x32.
// mma m16n8k8.tf32: warp = 4 mtiles x 4 ntiles.
#define LDA 20     // A smem row stride (floats): bank-conflict-free A frag loads
#define LDB 136    // B smem row stride (floats): bank-conflict-free B frag loads

__global__ __launch_bounds__(256, 2)
void gemm_tf32_kernel(const float* __restrict__ A, const float* __restrict__ W,
                      const float* __restrict__ bias, float* __restrict__ C,
                      int M, int N, int K)
{
    __shared__ float As[2][128][LDA];   // [m][k], k in 0..15
    __shared__ float Bs[2][16][LDB];    // [k][n], n in 0..127

    const int t    = threadIdx.x;
    const int wid  = t >> 5;
    const int lane = t & 31;
    const int g    = lane >> 2;   // 0..7
    const int tg   = lane & 3;    // 0..3
    const int wm   = wid & 1;     // 0..1
    const int wn   = wid >> 1;    // 0..3
    const int rowBase = blockIdx.y * 128;
    const int colBase = blockIdx.x * 128;

    // cp.async chunk indices (each thread: 2 A chunks + 2 B chunks of 16B)
    const int am0 = (2 * t + 0) >> 2, ak0 = ((2 * t + 0) & 3) * 4;
    const int am1 = (2 * t + 1) >> 2, ak1 = ((2 * t + 1) & 3) * 4;
    const int bk0 = (2 * t + 0) >> 5, bn0 = ((2 * t + 0) & 31) * 4;
    const int bk1 = (2 * t + 1) >> 5, bn1 = ((2 * t + 1) & 31) * 4;

    float acc[4][4][4];
    #pragma unroll
    for (int mi = 0; mi < 4; mi++)
        #pragma unroll
        for (int ni = 0; ni < 4; ni++)
            #pragma unroll
            for (int r = 0; r < 4; r++) acc[mi][ni][r] = 0.0f;

    const int NK = K / 16;

    // prologue: stage 0
    {
        const int k0 = 0;
        cp16(&As[0][am0][ak0], &A[(size_t)(rowBase + am0) * K + k0 + ak0]);
        cp16(&As[0][am1][ak1], &A[(size_t)(rowBase + am1) * K + k0 + ak1]);
        cp16(&Bs[0][bk0][bn0], &W[(size_t)(k0 + bk0) * N + colBase + bn0]);
        cp16(&Bs[0][bk1][bn1], &W[(size_t)(k0 + bk1) * N + colBase + bn1]);
        cp_commit();
    }

    for (int kt = 0; kt < NK; kt++) {
        cp_wait0();
        __syncthreads();

        // issue next stage loads (overlap with compute)
        if (kt + 1 < NK) {
            const int s  = (kt + 1) & 1;
            const int k0 = (kt + 1) * 16;
            cp16(&As[s][am0][ak0], &A[(size_t)(rowBase + am0) * K + k0 + ak0]);
            cp16(&As[s][am1][ak1], &A[(size_t)(rowBase + am1) * K + k0 + ak1]);
            cp16(&Bs[s][bk0][bn0], &W[(size_t)(k0 + bk0) * N + colBase + bn0]);
            cp16(&Bs[s][bk1][bn1], &W[(size_t)(k0 + bk1) * N + colBase + bn1]);
            cp_commit();
        }

        const int s = kt & 1;
        #pragma unroll
        for (int kstep = 0; kstep < 2; kstep++) {
            const int kk = kstep * 8 + tg;
            uint32_t af[4][4];
            #pragma unroll
            for (int mi = 0; mi < 4; mi++) {
                const int mr = wm * 64 + mi * 16 + g;
                af[mi][0] = f2tf(As[s][mr    ][kk    ]);
                af[mi][1] = f2tf(As[s][mr + 8][kk    ]);
                af[mi][2] = f2tf(As[s][mr    ][kk + 4]);
                af[mi][3] = f2tf(As[s][mr + 8][kk + 4]);
            }
            uint32_t bf[4][2];
            #pragma unroll
            for (int ni = 0; ni < 4; ni++) {
                const int nc = wn * 32 + ni * 8 + g;
                bf[ni][0] = f2tf(Bs[s][kk    ][nc]);
                bf[ni][1] = f2tf(Bs[s][kk + 4][nc]);
            }
            #pragma unroll
            for (int mi = 0; mi < 4; mi++)
                #pragma unroll
                for (int ni = 0; ni < 4; ni++)
                    mma_tf32(acc[mi][ni], af[mi][0], af[mi][1], af[mi][2], af[mi][3],
                             bf[ni][0], bf[ni][1]);
        }
    }

    // epilogue: add bias, store (float2 per row-half)
    #pragma unroll
    for (int mi = 0; mi < 4; mi++) {
        const int row0 = rowBase + wm * 64 + mi * 16 + g;
        #pragma unroll
        for (int ni = 0; ni < 4; ni++) {
            const int col = colBase + wn * 32 + ni * 8 + tg * 2;
            const float2 b2 = *(const float2*)&bias[col];
            float2 o0, o1;
            o0.x = acc[mi][ni][0] + b2.x;
            o0.y = acc[mi][ni][1] + b2.y;
            o1.x = acc[mi][ni][2] + b2.x;
            o1.y = acc[mi][ni][3] + b2.y;
            *(float2*)&C[(size_t)row0 * N + col]       = o0;
            *(float2*)&C[(size_t)(row0 + 8) * N + col] = o1;
        }
    }
}

// ---------------- RoPE tables ----------------
__global__ void freq_kernel(float* __restrict__ inv)
{
    int p = threadIdx.x;
    if (p < 64) inv[p] = (float)pow(10000.0, -(double)p / 64.0);
}

__global__ void trig_kernel(const float* __restrict__ inv,
                            float* __restrict__ ct, float* __restrict__ st)
{
    int idx = blockIdx.x * blockDim.x + threadIdx.x;
    if (idx >= TT * 64) return;
    int tpos = idx >> 6;
    int p    = idx & 63;
    float ang = (float)tpos * inv[p];
    float s, c;
    sincosf(ang, &s, &c);
    ct[idx] = c;
    st[idx] = s;
}

// ---------------- RoPE apply (k and q sections of g_kqv, in place) ----------------
__global__ void rope_kernel(float* __restrict__ kqv,
                            const float* __restrict__ ct, const float* __restrict__ st)
{
    int idx = blockIdx.x * blockDim.x + threadIdx.x;   // MROWS * DD pairs
    if (idx >= MROWS * DD) return;
    int row  = idx >> 11;          // / 2048
    int r    = idx & 2047;
    int sect = r >> 10;            // 0 = k, 1 = q
    int p    = r & 1023;           // pair index within section
    int h    = p >> 6;
    int pj   = p & 63;
    int tpos = row & (TT - 1);

    float c = ct[tpos * 64 + pj];
    float s = st[tpos * 64 + pj];

    size_t base = (size_t)row * N3 + (size_t)sect * DD + h * DK + 2 * pj;
    float2 v = *(float2*)&kqv[base];
    float2 o;
    o.x = v.x * c - v.y * s;
    o.y = v.x * s + v.y * c;
    *(float2*)&kqv[base] = o;
}

// ---------------- Flash attention (fp32, causal) ----------------
#define LDQ 132
#define LDK 68
#define LDP 129
#define ATTN_SMEM_FLOATS (128*LDQ + 128*LDK + 64*128 + 64*LDP)
#define ATTN_SMEM_BYTES  (ATTN_SMEM_FLOATS * 4)

__global__ __launch_bounds__(256, 1)
void attn_kernel()
{
    extern __shared__ float sm[];
    float* Qs = sm;                     // [128 d][LDQ]  (q-index inner)
    float* Ks = Qs + 128 * LDQ;         // [128 d][LDK]  (k-index inner)
    float* Vs = Ks + 128 * LDK;         // [64 k][128 d]
    float* Ps = Vs + 64 * 128;          // [64 k][LDP]   (q-index inner)

    const int t  = threadIdx.x;
    const int tx = t & 15;
    const int ty = t >> 4;
    const int bh = blockIdx.y;
    const int b  = bh >> 4;
    const int h  = bh & 15;
    const int qt = (int)gridDim.x - 1 - (int)blockIdx.x;   // heavy tiles first
    const int qbase = qt * 128;
    const size_t rowbase = (size_t)b * TT;
    const float scale = 0.08838834764831845f;  // 1/sqrt(128)

    // ---- load Q tile transposed: Qs[d][qi] ----
    for (int u = t; u < 128 * 32; u += 256) {
        int qi = u & 127;
        int dg = u >> 7;      // 0..31 (float4 of dims)
        const float* src = g_kqv + (rowbase + qbase + qi) * N3 + DD + h * DK + dg * 4;
        float4 v = *(const float4*)src;
        Qs[(dg * 4 + 0) * LDQ + qi] = v.x;
        Qs[(dg * 4 + 1) * LDQ + qi] = v.y;
        Qs[(dg * 4 + 2) * LDQ + qi] = v.z;
        Qs[(dg * 4 + 3) * LDQ + qi] = v.w;
    }

    float o[8][8];
    #pragma unroll
    for (int i = 0; i < 8; i++)
        #pragma unroll
        for (int j = 0; j < 8; j++) o[i][j] = 0.0f;
    float m[8], l[8];
    #pragma unroll
    for (int i = 0; i < 8; i++) { m[i] = -1e30f; l[i] = 0.0f; }

    const int nkt = 2 * qt + 2;
    for (int kt = 0; kt < nkt; kt++) {
        const int kbase = kt * 64;
        __syncthreads();   // previous iteration's O phase done with Ks/Vs/Ps

        // ---- K tile transposed: Ks[d][ki] ----
        for (int u = t; u < 64 * 32; u += 256) {
            int ki = u & 63;
            int dg = u >> 6;
            const float* src = g_kqv + (rowbase + kbase + ki) * N3 + h * DK + dg * 4;
            float4 v = *(const float4*)src;
            Ks[(dg * 4 + 0) * LDK + ki] = v.x;
            Ks[(dg * 4 + 1) * LDK + ki] = v.y;
            Ks[(dg * 4 + 2) * LDK + ki] = v.z;
            Ks[(dg * 4 + 3) * LDK + ki] = v.w;
        }
        // ---- V tile: Vs[ki][d] ----
        for (int u = t; u < 64 * 32; u += 256) {
            int ki = u >> 5;
            int dg = u & 31;
            const float* src = g_kqv + (rowbase + kbase + ki) * N3 + 2 * DD + h * DK + dg * 4;
            *(float4*)&Vs[ki * 128 + dg * 4] = *(const float4*)src;
        }
        __syncthreads();

        // ---- S = Q @ K^T : s[8 q][4 k] ----
        float s[8][4];
        #pragma unroll
        for (int i = 0; i < 8; i++)
            #pragma unroll
            for (int j = 0; j < 4; j++) s[i][j] = 0.0f;

        #pragma unroll 2
        for (int d = 0; d < 128; d++) {
            float a[8], bv[4];
            *(float4*)&a[0]  = *(const float4*)&Qs[d * LDQ + ty * 8];
            *(float4*)&a[4]  = *(const float4*)&Qs[d * LDQ + ty * 8 + 4];
            *(float4*)&bv[0] = *(const float4*)&Ks[d * LDK + tx * 4];
            #pragma unroll
            for (int i = 0; i < 8; i++)
                #pragma unroll
                for (int j = 0; j < 4; j++)
                    s[i][j] += a[i] * bv[j];
        }

        // ---- scale + causal mask + online softmax ----
        #pragma unroll
        for (int i = 0; i < 8; i++) {
            const int qrow = qbase + ty * 8 + i;
            #pragma unroll
            for (int j = 0; j < 4; j++) {
                float v = s[i][j] * scale;
                if (kbase + tx * 4 + j > qrow) v = -1e30f;
                s[i][j] = v;
            }
            float rm = fmaxf(fmaxf(s[i][0], s[i][1]), fmaxf(s[i][2], s[i][3]));
            rm = fmaxf(rm, __shfl_xor_sync(0xffffffffu, rm, 1));
            rm = fmaxf(rm, __shfl_xor_sync(0xffffffffu, rm, 2));
            rm = fmaxf(rm, __shfl_xor_sync(0xffffffffu, rm, 4));
            rm = fmaxf(rm, __shfl_xor_sync(0xffffffffu, rm, 8));
            const float mnew = fmaxf(m[i], rm);
            const float f = __expf(m[i] - mnew);
            m[i] = mnew;

            float ps = 0.0f;
            #pragma unroll
            for (int j = 0; j < 4; j++) {
                float p = __expf(s[i][j] - mnew);
                s[i][j] = p;
                ps += p;
            }
            ps += __shfl_xor_sync(0xffffffffu, ps, 1);
            ps += __shfl_xor_sync(0xffffffffu, ps, 2);
            ps += __shfl_xor_sync(0xffffffffu, ps, 4);
            ps += __shfl_xor_sync(0xffffffffu, ps, 8);
            l[i] = l[i] * f + ps;

            #pragma unroll
            for (int j = 0; j < 8; j++) o[i][j] *= f;

            #pragma unroll
            for (int j = 0; j < 4; j++)
                Ps[(tx * 4 + j) * LDP + ty * 8 + i] = s[i][j];
        }
        __syncthreads();

        // ---- O += P with V: o[8 q][8 d] ----
        #pragma unroll 2
        for (int k = 0; k < 64; k++) {
            float pv[8], vv[8];
            #pragma unroll
            for (int i = 0; i < 8; i++) pv[i] = Ps[k * LDP + ty * 8 + i];
            *(float4*)&vv[0] = *(const float4*)&Vs[k * 128 + tx * 8];
            *(float4*)&vv[4] = *(const float4*)&Vs[k * 128 + tx * 8 + 4];
            #pragma unroll
            for (int i = 0; i < 8; i++)
                #pragma unroll
                for (int j = 0; j < 8; j++)
                    o[i][j] += pv[i] * vv[j];
        }
    }

    // ---- epilogue: O / l -> g_attn ----
    #pragma unroll
    for (int i = 0; i < 8; i++) {
        const float invl = 1.0f / l[i];
        const size_t row = rowbase + qbase + ty * 8 + i;
        float* dst = g_attn + row * DD + h * DK + tx * 8;
        float4 o0, o1;
        o0.x = o[i][0] * invl; o0.y = o[i][1] * invl;
        o0.z = o[i][2] * invl; o0.w = o[i][3] * invl;
        o1.x = o[i][4] * invl; o1.y = o[i][5] * invl;
        o1.z = o[i][6] * invl; o1.w = o[i][7] * invl;
        *(float4*)&dst[0] = o0;
        *(float4*)&dst[4] = o1;
    }
}

// ---------------- launch ----------------
extern "C" void kernel_launch(void* const* d_in, const int* in_sizes, int n_in,
                              void* d_out, int out_size)
{
    const float* x    = (const float*)d_in[0];
    const float* Wkqv = (const float*)d_in[1];
    const float* bkqv = (const float*)d_in[2];
    const float* Wo   = (const float*)d_in[3];
    const float* bo   = (const float*)d_in[4];
    float* out = (float*)d_out;

    float *kqv, *attn, *inv, *ct, *st;
    cudaGetSymbolAddress((void**)&kqv,  g_kqv);
    cudaGetSymbolAddress((void**)&attn, g_attn);
    cudaGetSymbolAddress((void**)&inv,  g_inv);
    cudaGetSymbolAddress((void**)&ct,   g_cos);
    cudaGetSymbolAddress((void**)&st,   g_sin);

    cudaFuncSetAttribute(attn_kernel, cudaFuncAttributeMaxDynamicSharedMemorySize,
                         ATTN_SMEM_BYTES);

    // 1) kqv = x @ Wkqv + bkqv   (TF32 tensor cores)
    gemm_tf32_kernel<<<dim3(N3 / 128, MROWS / 128), 256>>>(x, Wkqv, bkqv, kqv,
                                                           MROWS, N3, DD);
    // 2) RoPE tables + apply to k,q
    freq_kernel<<<1, 64>>>(inv);
    trig_kernel<<<(TT * 64) / 256, 256>>>(inv, ct, st);
    rope_kernel<<<(MROWS * DD) / 256, 256>>>(kqv, ct, st);
    // 3) causal flash attention -> g_attn
    attn_kernel<<<dim3(TT / 128, BB * HH), 256, ATTN_SMEM_BYTES>>>();
    // 4) out = attn @ Wo + bo    (TF32 tensor cores)
    gemm_tf32_kernel<<<dim3(DD / 128, MROWS / 128), 256>>>(attn, Wo, bo, out,
                                                           MROWS, DD, DD);
}

// round 3
// speedup vs baseline: 2.8566x; 1.5561x over previous
#include <cuda_runtime.h>
#include <math.h>
#include <stdint.h>

#define BB    2
#define TT    2048
#define DD    2048
#define HH    16
#define DK    128
#define N3    (3*DD)
#define MROWS (BB*TT)   // 4096

// ---------------- scratch (device globals; no allocation allowed) ----------------
__device__ float g_kqv[(size_t)MROWS * N3];    // ~100 MB
__device__ float g_attn[(size_t)MROWS * DD];   // ~33 MB (tf32-rounded)
__device__ float g_xr[(size_t)MROWS * DD];     // x rounded to tf32
__device__ float g_wkr[(size_t)DD * N3];       // Wkqv rounded
__device__ float g_wor[(size_t)DD * DD];       // Wo rounded
__device__ float g_inv[64];
__device__ float g_cos[TT * 64];
__device__ float g_sin[TT * 64];

// ---------------- PTX helpers ----------------
__device__ __forceinline__ uint32_t smem_u32(const void* p) {
    return (uint32_t)__cvta_generic_to_shared(p);
}
__device__ __forceinline__ void cp16(void* dst, const void* src) {
    asm volatile("cp.async.cg.shared.global [%0], [%1], 16;\n"
                 :: "r"(smem_u32(dst)), "l"(src));
}
__device__ __forceinline__ void cp_commit() {
    asm volatile("cp.async.commit_group;\n");
}
template<int N>
__device__ __forceinline__ void cp_wait() {
    asm volatile("cp.async.wait_group %0;\n" :: "n"(N));
}
__device__ __forceinline__ uint32_t f2tf(float f) {
    uint32_t r;
    asm("cvt.rna.tf32.f32 %0, %1;" : "=r"(r) : "f"(f));
    return r;
}
__device__ __forceinline__ float tfr(float f) {       // round-to-tf32, as float
    return __uint_as_float(f2tf(f));
}
__device__ __forceinline__ void mma_tf32(float c[4],
                                         uint32_t a0, uint32_t a1, uint32_t a2, uint32_t a3,
                                         uint32_t b0, uint32_t b1) {
    asm volatile(
        "mma.sync.aligned.m16n8k8.row.col.f32.tf32.tf32.f32 "
        "{%0,%1,%2,%3}, {%4,%5,%6,%7}, {%8,%9}, {%0,%1,%2,%3};\n"
        : "+f"(c[0]), "+f"(c[1]), "+f"(c[2]), "+f"(c[3])
        : "r"(a0), "r"(a1), "r"(a2), "r"(a3), "r"(b0), "r"(b1));
}

// ---------------- tf32 rounding pass ----------------
__global__ void cvt_kernel(const float4* __restrict__ in, float4* __restrict__ out, int n4)
{
    int i = blockIdx.x * blockDim.x + threadIdx.x;
    if (i >= n4) return;
    float4 v = in[i];
    v.x = tfr(v.x); v.y = tfr(v.y); v.z = tfr(v.z); v.w = tfr(v.w);
    out[i] = v;
}

// ---------------- TF32 GEMM, inputs pre-rounded: C = A @ W + bias ----------------
#define LDA 20
#define LDB 136
#define GEMM_SMEM ((3*128*LDA + 3*16*LDB) * 4)

__global__ __launch_bounds__(256, 2)
void gemm_tf32_kernel(const float* __restrict__ A, const float* __restrict__ W,
                      const float* __restrict__ bias, float* __restrict__ C,
                      int M, int N, int K)
{
    extern __shared__ float gsm[];
    float* As = gsm;                   // [3][128][LDA]
    float* Bs = gsm + 3 * 128 * LDA;   // [3][16][LDB]

    const int t    = threadIdx.x;
    const int wid  = t >> 5;
    const int lane = t & 31;
    const int g    = lane >> 2;
    const int tg   = lane & 3;
    const int wm   = wid & 1;
    const int wn   = wid >> 1;
    const int rowBase = blockIdx.y * 128;
    const int colBase = blockIdx.x * 128;

    const int am0 = (2 * t + 0) >> 2, ak0 = ((2 * t + 0) & 3) * 4;
    const int am1 = (2 * t + 1) >> 2, ak1 = ((2 * t + 1) & 3) * 4;
    const int bk0 = (2 * t + 0) >> 5, bn0 = ((2 * t + 0) & 31) * 4;
    const int bk1 = (2 * t + 1) >> 5, bn1 = ((2 * t + 1) & 31) * 4;

    float acc[4][4][4];
    #pragma unroll
    for (int mi = 0; mi < 4; mi++)
        #pragma unroll
        for (int ni = 0; ni < 4; ni++)
            #pragma unroll
            for (int r = 0; r < 4; r++) acc[mi][ni][r] = 0.0f;

    const int NK = K / 16;

    auto issue = [&](int kt) {
        const int s  = kt % 3;
        const int k0 = kt * 16;
        cp16(&As[s * 128 * LDA + am0 * LDA + ak0], &A[(size_t)(rowBase + am0) * K + k0 + ak0]);
        cp16(&As[s * 128 * LDA + am1 * LDA + ak1], &A[(size_t)(rowBase + am1) * K + k0 + ak1]);
        cp16(&Bs[s * 16 * LDB + bk0 * LDB + bn0], &W[(size_t)(k0 + bk0) * N + colBase + bn0]);
        cp16(&Bs[s * 16 * LDB + bk1 * LDB + bn1], &W[(size_t)(k0 + bk1) * N + colBase + bn1]);
        cp_commit();
    };

    issue(0);
    issue(1);

    for (int kt = 0; kt < NK; kt++) {
        cp_wait<1>();
        __syncthreads();
        if (kt + 2 < NK) issue(kt + 2);

        const float* Asl = As + (kt % 3) * 128 * LDA;
        const float* Bsl = Bs + (kt % 3) * 16 * LDB;
        #pragma unroll
        for (int kstep = 0; kstep < 2; kstep++) {
            const int kk = kstep * 8 + tg;
            uint32_t af[4][4];
            #pragma unroll
            for (int mi = 0; mi < 4; mi++) {
                const int mr = wm * 64 + mi * 16 + g;
                af[mi][0] = *(const uint32_t*)&Asl[mr * LDA + kk];
                af[mi][1] = *(const uint32_t*)&Asl[(mr + 8) * LDA + kk];
                af[mi][2] = *(const uint32_t*)&Asl[mr * LDA + kk + 4];
                af[mi][3] = *(const uint32_t*)&Asl[(mr + 8) * LDA + kk + 4];
            }
            uint32_t bf[4][2];
            #pragma unroll
            for (int ni = 0; ni < 4; ni++) {
                const int nc = wn * 32 + ni * 8 + g;
                bf[ni][0] = *(const uint32_t*)&Bsl[kk * LDB + nc];
                bf[ni][1] = *(const uint32_t*)&Bsl[(kk + 4) * LDB + nc];
            }
            #pragma unroll
            for (int mi = 0; mi < 4; mi++)
                #pragma unroll
                for (int ni = 0; ni < 4; ni++)
                    mma_tf32(acc[mi][ni], af[mi][0], af[mi][1], af[mi][2], af[mi][3],
                             bf[ni][0], bf[ni][1]);
        }
        __syncthreads();
    }

    #pragma unroll
    for (int mi = 0; mi < 4; mi++) {
        const int row0 = rowBase + wm * 64 + mi * 16 + g;
        #pragma unroll
        for (int ni = 0; ni < 4; ni++) {
            const int col = colBase + wn * 32 + ni * 8 + tg * 2;
            const float2 b2 = *(const float2*)&bias[col];
            float2 o0, o1;
            o0.x = acc[mi][ni][0] + b2.x;
            o0.y = acc[mi][ni][1] + b2.y;
            o1.x = acc[mi][ni][2] + b2.x;
            o1.y = acc[mi][ni][3] + b2.y;
            *(float2*)&C[(size_t)row0 * N + col]       = o0;
            *(float2*)&C[(size_t)(row0 + 8) * N + col] = o1;
        }
    }
}

// ---------------- RoPE tables ----------------
__global__ void freq_kernel(float* __restrict__ inv)
{
    int p = threadIdx.x;
    if (p < 64) inv[p] = (float)pow(10000.0, -(double)p / 64.0);
}

__global__ void trig_kernel(const float* __restrict__ inv,
                            float* __restrict__ ct, float* __restrict__ st)
{
    int idx = blockIdx.x * blockDim.x + threadIdx.x;
    if (idx >= TT * 64) return;
    int tpos = idx >> 6;
    int p    = idx & 63;
    float ang = (float)tpos * inv[p];
    float s, c;
    sincosf(ang, &s, &c);
    ct[idx] = c;
    st[idx] = s;
}

// ---------------- RoPE apply (k,q) + tf32-round k,q,v ----------------
// grid (12, MROWS): 3072 pairs per row: [0,1024)=k [1024,2048)=q [2048,3072)=v
__global__ void rope2_kernel(float* __restrict__ kqv,
                             const float* __restrict__ ct, const float* __restrict__ st)
{
    const int row = blockIdx.y;
    const int r   = blockIdx.x * 256 + threadIdx.x;
    const int sect = r >> 10;
    const int p    = r & 1023;

    if (sect == 2) {   // v: just round
        size_t base = (size_t)row * N3 + 2 * DD + 2 * p;
        float2 v = *(float2*)&kqv[base];
        v.x = tfr(v.x); v.y = tfr(v.y);
        *(float2*)&kqv[base] = v;
        return;
    }
    const int h    = p >> 6;
    const int pj   = p & 63;
    const int tpos = row & (TT - 1);
    const float c = ct[tpos * 64 + pj];
    const float s = st[tpos * 64 + pj];
    size_t base = (size_t)row * N3 + (size_t)sect * DD + h * DK + 2 * pj;
    float2 v = *(float2*)&kqv[base];
    float2 o;
    o.x = tfr(v.x * c - v.y * s);
    o.y = tfr(v.x * s + v.y * c);
    *(float2*)&kqv[base] = o;
}

// ---------------- Flash attention (tf32 tensor cores, causal) ----------------
// 256 threads (8 warps); CTA = 128 q rows of one (b,h); ktile = 64 keys.
// Warp = 16 q rows; S warp tile 16x64 (8 ntiles); PV warp tile 16x128 (16 ntiles).
#define LDKK 132
#define LDVV 136
#define LDPK 132
#define ATT_SMEM ((2*64*LDKK + 2*64*LDVV + 128*LDPK) * 4)   // 200 KB

__global__ __launch_bounds__(256, 1)
void attn_mma_kernel()
{
    extern __shared__ float sm[];
    float* Ks = sm;                                  // [2][64][LDKK]
    float* Vs = Ks + 2 * 64 * LDKK;                  // [2][64][LDVV]
    float* Ps = Vs + 2 * 64 * LDVV;                  // [128][LDPK] (also Q staging)

    const int t    = threadIdx.x;
    const int lane = t & 31;
    const int w    = t >> 5;       // warp 0..7
    const int g    = lane >> 2;    // 0..7
    const int tg   = lane & 3;     // 0..3
    const int bh = blockIdx.y;
    const int b  = bh >> 4;
    const int h  = bh & 15;
    const int qt = (int)gridDim.x - 1 - (int)blockIdx.x;   // heavy first
    const int qbase = qt * 128;
    const size_t rowbase = (size_t)b * TT;
    const int hoff = h * DK;
    const float scale = 0.08838834764831845f;  // 1/sqrt(128)

    // ---- stage Q tile into Ps, then load Q fragments to registers ----
    for (int u = t; u < 128 * 32; u += 256) {
        int qi = u >> 5;
        int c  = u & 31;
        float4 v = *(const float4*)&g_kqv[(rowbase + qbase + qi) * N3 + DD + hoff + c * 4];
        *(float4*)&Ps[qi * LDPK + c * 4] = v;
    }
    __syncthreads();
    const int qr = w * 16 + g;
    uint32_t qf[16][4];
    #pragma unroll
    for (int ks = 0; ks < 16; ks++) {
        qf[ks][0] = *(const uint32_t*)&Ps[qr * LDPK + ks * 8 + tg];
        qf[ks][1] = *(const uint32_t*)&Ps[(qr + 8) * LDPK + ks * 8 + tg];
        qf[ks][2] = *(const uint32_t*)&Ps[qr * LDPK + ks * 8 + tg + 4];
        qf[ks][3] = *(const uint32_t*)&Ps[(qr + 8) * LDPK + ks * 8 + tg + 4];
    }
    __syncthreads();

    float oacc[16][4];
    #pragma unroll
    for (int ni = 0; ni < 16; ni++)
        #pragma unroll
        for (int r = 0; r < 4; r++) oacc[ni][r] = 0.0f;
    float m0 = -1e30f, m1 = -1e30f, l0 = 0.0f, l1 = 0.0f;

    auto issue_tile = [&](int kt) {
        const int s = kt & 1;
        #pragma unroll
        for (int i = 0; i < 8; i++) {
            int u = t + i * 256;
            int r = u >> 5;
            int c = u & 31;
            const size_t grow = (rowbase + (size_t)kt * 64 + r) * N3;
            cp16(&Ks[s * 64 * LDKK + r * LDKK + c * 4], &g_kqv[grow + hoff + c * 4]);
            cp16(&Vs[s * 64 * LDVV + r * LDVV + c * 4], &g_kqv[grow + 2 * DD + hoff + c * 4]);
        }
        cp_commit();
    };

    const int nkt = 2 * qt + 2;
    issue_tile(0);

    for (int kt = 0; kt < nkt; kt++) {
        const int s = kt & 1;
        __syncthreads();                       // prior PV / P readers done
        if (kt + 1 < nkt) issue_tile(kt + 1);
        cp_wait<1>();
        __syncthreads();                       // K/V[kt] visible

        // ---- S = Q @ K^T ----
        float sacc[8][4];
        #pragma unroll
        for (int ni = 0; ni < 8; ni++)
            #pragma unroll
            for (int r = 0; r < 4; r++) sacc[ni][r] = 0.0f;

        const float* Kb = Ks + s * 64 * LDKK;
        #pragma unroll
        for (int ks = 0; ks < 16; ks++) {
            #pragma unroll
            for (int ni = 0; ni < 8; ni++) {
                uint32_t b0 = *(const uint32_t*)&Kb[(ni * 8 + g) * LDKK + ks * 8 + tg];
                uint32_t b1 = *(const uint32_t*)&Kb[(ni * 8 + g) * LDKK + ks * 8 + tg + 4];
                mma_tf32(sacc[ni], qf[ks][0], qf[ks][1], qf[ks][2], qf[ks][3], b0, b1);
            }
        }

        // ---- scale + causal mask + online softmax ----
        const int r0 = qbase + w * 16 + g;
        const int r1 = r0 + 8;
        const int kb = kt * 64;
        float rm0 = -1e30f, rm1 = -1e30f;
        #pragma unroll
        for (int ni = 0; ni < 8; ni++) {
            const int c0 = kb + ni * 8 + 2 * tg;
            float v0 = sacc[ni][0] * scale; if (c0     > r0) v0 = -1e30f;
            float v1 = sacc[ni][1] * scale; if (c0 + 1 > r0) v1 = -1e30f;
            float v2 = sacc[ni][2] * scale; if (c0     > r1) v2 = -1e30f;
            float v3 = sacc[ni][3] * scale; if (c0 + 1 > r1) v3 = -1e30f;
            sacc[ni][0] = v0; sacc[ni][1] = v1; sacc[ni][2] = v2; sacc[ni][3] = v3;
            rm0 = fmaxf(rm0, fmaxf(v0, v1));
            rm1 = fmaxf(rm1, fmaxf(v2, v3));
        }
        rm0 = fmaxf(rm0, __shfl_xor_sync(0xffffffffu, rm0, 1));
        rm0 = fmaxf(rm0, __shfl_xor_sync(0xffffffffu, rm0, 2));
        rm1 = fmaxf(rm1, __shfl_xor_sync(0xffffffffu, rm1, 1));
        rm1 = fmaxf(rm1, __shfl_xor_sync(0xffffffffu, rm1, 2));

        const float mn0 = fmaxf(m0, rm0);
        const float mn1 = fmaxf(m1, rm1);
        const float f0 = __expf(m0 - mn0);
        const float f1 = __expf(m1 - mn1);
        m0 = mn0; m1 = mn1;

        float ps0 = 0.0f, ps1 = 0.0f;
        #pragma unroll
        for (int ni = 0; ni < 8; ni++) {
            float p0 = __expf(sacc[ni][0] - mn0);
            float p1 = __expf(sacc[ni][1] - mn0);
            float p2 = __expf(sacc[ni][2] - mn1);
            float p3 = __expf(sacc[ni][3] - mn1);
            sacc[ni][0] = p0; sacc[ni][1] = p1; sacc[ni][2] = p2; sacc[ni][3] = p3;
            ps0 += p0 + p1;
            ps1 += p2 + p3;
        }
        ps0 += __shfl_xor_sync(0xffffffffu, ps0, 1);
        ps0 += __shfl_xor_sync(0xffffffffu, ps0, 2);
        ps1 += __shfl_xor_sync(0xffffffffu, ps1, 1);
        ps1 += __shfl_xor_sync(0xffffffffu, ps1, 2);
        l0 = l0 * f0 + ps0;
        l1 = l1 * f1 + ps1;

        #pragma unroll
        for (int ni = 0; ni < 16; ni++) {
            oacc[ni][0] *= f0; oacc[ni][1] *= f0;
            oacc[ni][2] *= f1; oacc[ni][3] *= f1;
        }

        // ---- store P (full fp32) ----
        const int pq = w * 16 + g;
        #pragma unroll
        for (int ni = 0; ni < 8; ni++) {
            *(float2*)&Ps[pq * LDPK + ni * 8 + 2 * tg]       = make_float2(sacc[ni][0], sacc[ni][1]);
            *(float2*)&Ps[(pq + 8) * LDPK + ni * 8 + 2 * tg] = make_float2(sacc[ni][2], sacc[ni][3]);
        }
        __syncthreads();

        // ---- O += P @ V  (P hi/lo split: near-fp32 precision) ----
        const float* Vb = Vs + s * 64 * LDVV;
        #pragma unroll
        for (int ks2 = 0; ks2 < 8; ks2++) {
            float a0 = Ps[pq * LDPK + ks2 * 8 + tg];
            float a1 = Ps[(pq + 8) * LDPK + ks2 * 8 + tg];
            float a2 = Ps[pq * LDPK + ks2 * 8 + tg + 4];
            float a3 = Ps[(pq + 8) * LDPK + ks2 * 8 + tg + 4];
            uint32_t h0 = f2tf(a0), h1 = f2tf(a1), h2 = f2tf(a2), h3 = f2tf(a3);
            uint32_t e0 = f2tf(a0 - __uint_as_float(h0));
            uint32_t e1 = f2tf(a1 - __uint_as_float(h1));
            uint32_t e2 = f2tf(a2 - __uint_as_float(h2));
            uint32_t e3 = f2tf(a3 - __uint_as_float(h3));
            #pragma unroll
            for (int ni = 0; ni < 16; ni++) {
                uint32_t b0 = *(const uint32_t*)&Vb[(ks2 * 8 + tg) * LDVV + ni * 8 + g];
                uint32_t b1 = *(const uint32_t*)&Vb[(ks2 * 8 + tg + 4) * LDVV + ni * 8 + g];
                mma_tf32(oacc[ni], h0, h1, h2, h3, b0, b1);
                mma_tf32(oacc[ni], e0, e1, e2, e3, b0, b1);
            }
        }
    }

    // ---- epilogue: O/l, tf32-round, store ----
    const float il0 = 1.0f / l0;
    const float il1 = 1.0f / l1;
    const size_t row0 = rowbase + qbase + w * 16 + g;
    #pragma unroll
    for (int ni = 0; ni < 16; ni++) {
        const int col = hoff + ni * 8 + 2 * tg;
        float2 o0, o1;
        o0.x = tfr(oacc[ni][0] * il0);
        o0.y = tfr(oacc[ni][1] * il0);
        o1.x = tfr(oacc[ni][2] * il1);
        o1.y = tfr(oacc[ni][3] * il1);
        *(float2*)&g_attn[row0 * DD + col]       = o0;
        *(float2*)&g_attn[(row0 + 8) * DD + col] = o1;
    }
}

// ---------------- launch ----------------
extern "C" void kernel_launch(void* const* d_in, const int* in_sizes, int n_in,
                              void* d_out, int out_size)
{
    const float* x    = (const float*)d_in[0];
    const float* Wkqv = (const float*)d_in[1];
    const float* bkqv = (const float*)d_in[2];
    const float* Wo   = (const float*)d_in[3];
    const float* bo   = (const float*)d_in[4];
    float* out = (float*)d_out;

    float *kqv, *attn, *xr, *wkr, *wor, *inv, *ct, *st;
    cudaGetSymbolAddress((void**)&kqv,  g_kqv);
    cudaGetSymbolAddress((void**)&attn, g_attn);
    cudaGetSymbolAddress((void**)&xr,   g_xr);
    cudaGetSymbolAddress((void**)&wkr,  g_wkr);
    cudaGetSymbolAddress((void**)&wor,  g_wor);
    cudaGetSymbolAddress((void**)&inv,  g_inv);
    cudaGetSymbolAddress((void**)&ct,   g_cos);
    cudaGetSymbolAddress((void**)&st,   g_sin);

    cudaFuncSetAttribute(gemm_tf32_kernel, cudaFuncAttributeMaxDynamicSharedMemorySize, GEMM_SMEM);
    cudaFuncSetAttribute(attn_mma_kernel,  cudaFuncAttributeMaxDynamicSharedMemorySize, ATT_SMEM);

    // 0) round inputs to tf32 once
    cvt_kernel<<<(MROWS * DD / 4) / 256, 256>>>((const float4*)x,    (float4*)xr,  MROWS * DD / 4);
    cvt_kernel<<<(DD * N3 / 4) / 256, 256>>>((const float4*)Wkqv, (float4*)wkr, DD * N3 / 4);
    cvt_kernel<<<(DD * DD / 4) / 256, 256>>>((const float4*)Wo,   (float4*)wor, DD * DD / 4);

    // 1) kqv = x @ Wkqv + bkqv
    gemm_tf32_kernel<<<dim3(N3 / 128, MROWS / 128), 256, GEMM_SMEM>>>(xr, wkr, bkqv, kqv,
                                                                      MROWS, N3, DD);
    // 2) RoPE tables + apply (also tf32-rounds k,q,v)
    freq_kernel<<<1, 64>>>(inv);
    trig_kernel<<<(TT * 64) / 256, 256>>>(inv, ct, st);
    rope2_kernel<<<dim3(12, MROWS), 256>>>(kqv, ct, st);
    // 3) causal flash attention (tensor cores) -> g_attn (tf32-rounded)
    attn_mma_kernel<<<dim3(TT / 128, BB * HH), 256, ATT_SMEM>>>();
    // 4) out = attn @ Wo + bo
    gemm_tf32_kernel<<<dim3(DD / 128, MROWS / 128), 256, GEMM_SMEM>>>(attn, wor, bo, out,
                                                                     MROWS, DD, DD);
}

// round 5
// speedup vs baseline: 3.3156x; 1.1607x over previous
#include <cuda_runtime.h>
#include <math.h>
#include <stdint.h>

#define BB    2
#define TT    2048
#define DD    2048
#define HH    16
#define DK    128
#define N3    (3*DD)
#define MROWS (BB*TT)   // 4096

// ---------------- scratch (device globals; no allocation allowed) ----------------
__device__ float g_kqv[(size_t)MROWS * N3];    // fp32 k|q|v (tf32-rounded, rope applied)
__device__ float g_attn[(size_t)MROWS * DD];   // attention output fp32
__device__ float g_xp[(size_t)MROWS * DD];     // x packed (tf32)   [ck][M] float4 cells
__device__ float g_wkp[(size_t)DD * N3];       // Wkqv packed       [ck][N] float4 cells
__device__ float g_wop[(size_t)DD * DD];       // Wo packed
__device__ float g_ap[(size_t)MROWS * DD];     // attn packed
__device__ float g_inv[64];
__device__ float g_cos[TT * 64];
__device__ float g_sin[TT * 64];

// ---------------- PTX helpers ----------------
__device__ __forceinline__ uint32_t smem_u32(const void* p) {
    return (uint32_t)__cvta_generic_to_shared(p);
}
__device__ __forceinline__ void cp16s(uint32_t dst, const void* src) {
    asm volatile("cp.async.cg.shared.global [%0], [%1], 16;\n" :: "r"(dst), "l"(src));
}
__device__ __forceinline__ void cp16(void* dst, const void* src) {
    asm volatile("cp.async.cg.shared.global [%0], [%1], 16;\n"
                 :: "r"(smem_u32(dst)), "l"(src));
}
__device__ __forceinline__ void cp_commit() {
    asm volatile("cp.async.commit_group;\n");
}
template<int N>
__device__ __forceinline__ void cp_wait() {
    asm volatile("cp.async.wait_group %0;\n" :: "n"(N));
}
__device__ __forceinline__ uint32_t f2tf(float f) {
    uint32_t r;
    asm("cvt.rna.tf32.f32 %0, %1;" : "=r"(r) : "f"(f));
    return r;
}
__device__ __forceinline__ float tfr(float f) {
    return __uint_as_float(f2tf(f));
}
__device__ __forceinline__ void mma_tf32(float c[4],
                                         uint32_t a0, uint32_t a1, uint32_t a2, uint32_t a3,
                                         uint32_t b0, uint32_t b1) {
    asm volatile(
        "mma.sync.aligned.m16n8k8.row.col.f32.tf32.tf32.f32 "
        "{%0,%1,%2,%3}, {%4,%5,%6,%7}, {%8,%9}, {%0,%1,%2,%3};\n"
        : "+f"(c[0]), "+f"(c[1]), "+f"(c[2]), "+f"(c[3])
        : "r"(a0), "r"(a1), "r"(a2), "r"(a3), "r"(b0), "r"(b1));
}
#define FU(x) __float_as_uint(x)

// ---------------- pack kernels: fragment-order gmem layout ----------------
// Cell (ck, i) with ck = kg*4+tg holds (X[i][kb], X[i][kb+4], X[i][kb+8], X[i][kb+12]),
// kb = kg*16+tg, stored as float4 at out[ck*Len + i]. All values tf32(rna)-rounded.

// A-side pack (A row-major [Mt][K]) via 32x64 smem tile for coalesced IO.
__global__ void packA_kernel(const float* __restrict__ in, float4* __restrict__ out,
                             int Mt, int K)
{
    __shared__ float tile[32][65];
    const int k0 = blockIdx.x * 64;
    const int m0 = blockIdx.y * 32;
    const int t  = threadIdx.x;
    #pragma unroll
    for (int i = 0; i < 2; i++) {
        int u = t + (i << 8);          // 0..511 : 32 m x 16 float4
        int m = u >> 4;
        int kc = u & 15;
        float4 v = *(const float4*)&in[(size_t)(m0 + m) * K + k0 + kc * 4];
        tile[m][kc * 4 + 0] = v.x;
        tile[m][kc * 4 + 1] = v.y;
        tile[m][kc * 4 + 2] = v.z;
        tile[m][kc * 4 + 3] = v.w;
    }
    __syncthreads();
    #pragma unroll
    for (int i = 0; i < 2; i++) {
        int u  = t + (i << 8);         // 0..511 : 16 ck x 32 m
        int ck = u >> 5;
        int m  = u & 31;
        int kg = ck >> 2, tg = ck & 3;
        int kb = kg * 16 + tg;
        float4 v;
        v.x = tfr(tile[m][kb]);
        v.y = tfr(tile[m][kb + 4]);
        v.z = tfr(tile[m][kb + 8]);
        v.w = tfr(tile[m][kb + 12]);
        out[(size_t)((k0 / 16 + kg) * 4 + tg) * Mt + m0 + m] = v;
    }
}

// B-side pack (W row-major [K][N]) — reads are 4 coalesced streams.
__global__ void packB_kernel(const float* __restrict__ W, float4* __restrict__ out,
                             int K, int N)
{
    int idx = blockIdx.x * 256 + threadIdx.x;
    int total = (K / 4) * N;           // (K/16)*4 cells-rows * N
    if (idx >= total) return;
    int ck = idx / N;
    int n  = idx - ck * N;
    int kg = ck >> 2, tg = ck & 3;
    int kb = kg * 16 + tg;
    float4 v;
    v.x = tfr(W[(size_t)kb * N + n]);
    v.y = tfr(W[(size_t)(kb + 4) * N + n]);
    v.z = tfr(W[(size_t)(kb + 8) * N + n]);
    v.w = tfr(W[(size_t)(kb + 12) * N + n]);
    out[(size_t)ck * N + n] = v;
}

// ---------------- packed TF32 GEMM: C[M,N] = A @ W + bias (+optional fused RoPE) ----------------
// CTA 128x128, 8 warps (2m x 4n), warp tile 64x32, BK=16, 3-stage cp.async.
// Smem per stage: A 4*130 cells + B 4*130 cells (16B cells, stride 130 => conflict-free LDS.128).
#define STAGE_BYTES 8320                      // 4*130*16
#define GEMM_SMEM   (6 * STAGE_BYTES)         // 49920

__global__ __launch_bounds__(256, 2)
void gemm_packed_kernel(const float4* __restrict__ Ap, const float4* __restrict__ Bp,
                        const float* __restrict__ bias, float* __restrict__ C,
                        int Mt, int Nt, int K, int mode,
                        const float* __restrict__ ct, const float* __restrict__ st)
{
    extern __shared__ char smx[];
    const uint32_t sb = smem_u32(smx);
    const int t    = threadIdx.x;
    const int wid  = t >> 5;
    const int lane = t & 31;
    const int g    = lane >> 2;
    const int tg   = lane & 3;
    const int wm   = wid & 1;
    const int wn   = wid >> 1;
    const int rowBase = blockIdx.y * 128;
    const int colBase = blockIdx.x * 128;

    float acc[4][4][4];
    #pragma unroll
    for (int mi = 0; mi < 4; mi++)
        #pragma unroll
        for (int ni = 0; ni < 4; ni++)
            #pragma unroll
            for (int r = 0; r < 4; r++) acc[mi][ni][r] = 0.0f;

    const int NK = K / 16;

    auto issue = [&](int kt) {
        const int s = kt % 3;
        #pragma unroll
        for (int i = 0; i < 4; i++) {
            const int u   = t + (i << 8);            // 0..1023
            const int tg4 = (u >> 7) & 3;
            const int mm  = u & 127;
            if (u < 512) {
                uint32_t dst = sb + s * STAGE_BYTES + (tg4 * 130 + mm) * 16;
                cp16s(dst, Ap + ((size_t)(kt * 4 + tg4) * Mt + rowBase + mm));
            } else {
                uint32_t dst = sb + 3 * STAGE_BYTES + s * STAGE_BYTES + (tg4 * 130 + mm) * 16;
                cp16s(dst, Bp + ((size_t)(kt * 4 + tg4) * Nt + colBase + mm));
            }
        }
        cp_commit();
    };

    issue(0);
    issue(1);

    for (int kt = 0; kt < NK; kt++) {
        cp_wait<1>();
        __syncthreads();
        if (kt + 2 < NK) issue(kt + 2);

        const float* Asl = (const float*)(smx + (kt % 3) * STAGE_BYTES);
        const float* Bsl = (const float*)(smx + 3 * STAGE_BYTES + (kt % 3) * STAGE_BYTES);

        float4 A0[4], A1[4], Bv[4];
        #pragma unroll
        for (int mi = 0; mi < 4; mi++) {
            const int mr = wm * 64 + mi * 16 + g;
            A0[mi] = *(const float4*)&Asl[(tg * 130 + mr) * 4];
            A1[mi] = *(const float4*)&Asl[(tg * 130 + mr + 8) * 4];
        }
        #pragma unroll
        for (int ni = 0; ni < 4; ni++)
            Bv[ni] = *(const float4*)&Bsl[(tg * 130 + wn * 32 + ni * 8 + g) * 4];

        #pragma unroll
        for (int mi = 0; mi < 4; mi++)
            #pragma unroll
            for (int ni = 0; ni < 4; ni++) {
                mma_tf32(acc[mi][ni], FU(A0[mi].x), FU(A1[mi].x), FU(A0[mi].y), FU(A1[mi].y),
                         FU(Bv[ni].x), FU(Bv[ni].y));
                mma_tf32(acc[mi][ni], FU(A0[mi].z), FU(A1[mi].z), FU(A0[mi].w), FU(A1[mi].w),
                         FU(Bv[ni].z), FU(Bv[ni].w));
            }
        __syncthreads();
    }
    cp_wait<0>();

    // ---- epilogue: bias (+fused rope + tf32 rounding when mode==1) ----
    #pragma unroll
    for (int mi = 0; mi < 4; mi++) {
        const int r0 = rowBase + wm * 64 + mi * 16 + g;
        const int r1 = r0 + 8;
        #pragma unroll
        for (int ni = 0; ni < 4; ni++) {
            const int c = colBase + wn * 32 + ni * 8 + tg * 2;
            const float2 b2 = *(const float2*)&bias[c];
            float v0 = acc[mi][ni][0] + b2.x;
            float v1 = acc[mi][ni][1] + b2.y;
            float v2 = acc[mi][ni][2] + b2.x;
            float v3 = acc[mi][ni][3] + b2.y;
            if (mode == 1) {
                const int sect = c >> 11;
                if (sect < 2) {           // k or q: apply rope
                    const int pj = (c & 127) >> 1;
                    const float c0 = ct[(r0 & (TT - 1)) * 64 + pj];
                    const float s0 = st[(r0 & (TT - 1)) * 64 + pj];
                    const float c1 = ct[(r1 & (TT - 1)) * 64 + pj];
                    const float s1 = st[(r1 & (TT - 1)) * 64 + pj];
                    float e0 = v0 * c0 - v1 * s0, o0 = v0 * s0 + v1 * c0;
                    float e1 = v2 * c1 - v3 * s1, o1 = v2 * s1 + v3 * c1;
                    v0 = e0; v1 = o0; v2 = e1; v3 = o1;
                }
                v0 = tfr(v0); v1 = tfr(v1); v2 = tfr(v2); v3 = tfr(v3);
            }
            *(float2*)&C[(size_t)r0 * Nt + c] = make_float2(v0, v1);
            *(float2*)&C[(size_t)r1 * Nt + c] = make_float2(v2, v3);
        }
    }
}

// ---------------- RoPE tables ----------------
__global__ void freq_kernel(float* __restrict__ inv)
{
    int p = threadIdx.x;
    if (p < 64) inv[p] = (float)pow(10000.0, -(double)p / 64.0);
}

__global__ void trig_kernel(const float* __restrict__ inv,
                            float* __restrict__ ct, float* __restrict__ st)
{
    int idx = blockIdx.x * blockDim.x + threadIdx.x;
    if (idx >= TT * 64) return;
    int tpos = idx >> 6;
    int p    = idx & 63;
    float ang = (float)tpos * inv[p];
    float s, c;
    sincosf(ang, &s, &c);
    ct[idx] = c;
    st[idx] = s;
}

// ---------------- Flash attention (tf32 tensor cores, causal) ----------------
#define LDKK 132
#define LDVV 136
#define LDPK 132
#define ATT_SMEM ((2*64*LDKK + 2*64*LDVV + 128*LDPK) * 4)   // 200 KB

__global__ __launch_bounds__(256, 1)
void attn_mma_kernel()
{
    extern __shared__ float sm[];
    float* Ks = sm;                                  // [2][64][LDKK]
    float* Vs = Ks + 2 * 64 * LDKK;                  // [2][64][LDVV]
    float* Ps = Vs + 2 * 64 * LDVV;                  // [128][LDPK] (also Q staging)

    const int t    = threadIdx.x;
    const int lane = t & 31;
    const int w    = t >> 5;
    const int g    = lane >> 2;
    const int tg   = lane & 3;
    const int bh = blockIdx.y;
    const int b  = bh >> 4;
    const int h  = bh & 15;
    const int qt = (int)gridDim.x - 1 - (int)blockIdx.x;
    const int qbase = qt * 128;
    const size_t rowbase = (size_t)b * TT;
    const int hoff = h * DK;
    const float scale = 0.08838834764831845f;

    for (int u = t; u < 128 * 32; u += 256) {
        int qi = u >> 5;
        int c  = u & 31;
        float4 v = *(const float4*)&g_kqv[(rowbase + qbase + qi) * N3 + DD + hoff + c * 4];
        *(float4*)&Ps[qi * LDPK + c * 4] = v;
    }
    __syncthreads();
    const int qr = w * 16 + g;
    uint32_t qf[16][4];
    #pragma unroll
    for (int ks = 0; ks < 16; ks++) {
        qf[ks][0] = *(const uint32_t*)&Ps[qr * LDPK + ks * 8 + tg];
        qf[ks][1] = *(const uint32_t*)&Ps[(qr + 8) * LDPK + ks * 8 + tg];
        qf[ks][2] = *(const uint32_t*)&Ps[qr * LDPK + ks * 8 + tg + 4];
        qf[ks][3] = *(const uint32_t*)&Ps[(qr + 8) * LDPK + ks * 8 + tg + 4];
    }
    __syncthreads();

    float oacc[16][4];
    #pragma unroll
    for (int ni = 0; ni < 16; ni++)
        #pragma unroll
        for (int r = 0; r < 4; r++) oacc[ni][r] = 0.0f;
    float m0 = -1e30f, m1 = -1e30f, l0 = 0.0f, l1 = 0.0f;

    auto issue_tile = [&](int kt) {
        const int s = kt & 1;
        #pragma unroll
        for (int i = 0; i < 8; i++) {
            int u = t + i * 256;
            int r = u >> 5;
            int c = u & 31;
            const size_t grow = (rowbase + (size_t)kt * 64 + r) * N3;
            cp16(&Ks[s * 64 * LDKK + r * LDKK + c * 4], &g_kqv[grow + hoff + c * 4]);
            cp16(&Vs[s * 64 * LDVV + r * LDVV + c * 4], &g_kqv[grow + 2 * DD + hoff + c * 4]);
        }
        cp_commit();
    };

    const int nkt = 2 * qt + 2;
    issue_tile(0);

    for (int kt = 0; kt < nkt; kt++) {
        const int s = kt & 1;
        __syncthreads();
        if (kt + 1 < nkt) issue_tile(kt + 1);
        cp_wait<1>();
        __syncthreads();

        float sacc[8][4];
        #pragma unroll
        for (int ni = 0; ni < 8; ni++)
            #pragma unroll
            for (int r = 0; r < 4; r++) sacc[ni][r] = 0.0f;

        const float* Kb = Ks + s * 64 * LDKK;
        #pragma unroll
        for (int ks = 0; ks < 16; ks++) {
            #pragma unroll
            for (int ni = 0; ni < 8; ni++) {
                uint32_t b0 = *(const uint32_t*)&Kb[(ni * 8 + g) * LDKK + ks * 8 + tg];
                uint32_t b1 = *(const uint32_t*)&Kb[(ni * 8 + g) * LDKK + ks * 8 + tg + 4];
                mma_tf32(sacc[ni], qf[ks][0], qf[ks][1], qf[ks][2], qf[ks][3], b0, b1);
            }
        }

        const int r0 = qbase + w * 16 + g;
        const int r1 = r0 + 8;
        const int kb = kt * 64;
        float rm0 = -1e30f, rm1 = -1e30f;
        #pragma unroll
        for (int ni = 0; ni < 8; ni++) {
            const int c0 = kb + ni * 8 + 2 * tg;
            float v0 = sacc[ni][0] * scale; if (c0     > r0) v0 = -1e30f;
            float v1 = sacc[ni][1] * scale; if (c0 + 1 > r0) v1 = -1e30f;
            float v2 = sacc[ni][2] * scale; if (c0     > r1) v2 = -1e30f;
            float v3 = sacc[ni][3] * scale; if (c0 + 1 > r1) v3 = -1e30f;
            sacc[ni][0] = v0; sacc[ni][1] = v1; sacc[ni][2] = v2; sacc[ni][3] = v3;
            rm0 = fmaxf(rm0, fmaxf(v0, v1));
            rm1 = fmaxf(rm1, fmaxf(v2, v3));
        }
        rm0 = fmaxf(rm0, __shfl_xor_sync(0xffffffffu, rm0, 1));
        rm0 = fmaxf(rm0, __shfl_xor_sync(0xffffffffu, rm0, 2));
        rm1 = fmaxf(rm1, __shfl_xor_sync(0xffffffffu, rm1, 1));
        rm1 = fmaxf(rm1, __shfl_xor_sync(0xffffffffu, rm1, 2));

        const float mn0 = fmaxf(m0, rm0);
        const float mn1 = fmaxf(m1, rm1);
        const float f0 = __expf(m0 - mn0);
        const float f1 = __expf(m1 - mn1);
        m0 = mn0; m1 = mn1;

        float ps0 = 0.0f, ps1 = 0.0f;
        #pragma unroll
        for (int ni = 0; ni < 8; ni++) {
            float p0 = __expf(sacc[ni][0] - mn0);
            float p1 = __expf(sacc[ni][1] - mn0);
            float p2 = __expf(sacc[ni][2] - mn1);
            float p3 = __expf(sacc[ni][3] - mn1);
            sacc[ni][0] = p0; sacc[ni][1] = p1; sacc[ni][2] = p2; sacc[ni][3] = p3;
            ps0 += p0 + p1;
            ps1 += p2 + p3;
        }
        ps0 += __shfl_xor_sync(0xffffffffu, ps0, 1);
        ps0 += __shfl_xor_sync(0xffffffffu, ps0, 2);
        ps1 += __shfl_xor_sync(0xffffffffu, ps1, 1);
        ps1 += __shfl_xor_sync(0xffffffffu, ps1, 2);
        l0 = l0 * f0 + ps0;
        l1 = l1 * f1 + ps1;

        #pragma unroll
        for (int ni = 0; ni < 16; ni++) {
            oacc[ni][0] *= f0; oacc[ni][1] *= f0;
            oacc[ni][2] *= f1; oacc[ni][3] *= f1;
        }

        const int pq = w * 16 + g;
        #pragma unroll
        for (int ni = 0; ni < 8; ni++) {
            *(float2*)&Ps[pq * LDPK + ni * 8 + 2 * tg]       = make_float2(sacc[ni][0], sacc[ni][1]);
            *(float2*)&Ps[(pq + 8) * LDPK + ni * 8 + 2 * tg] = make_float2(sacc[ni][2], sacc[ni][3]);
        }
        __syncthreads();

        const float* Vb = Vs + s * 64 * LDVV;
        #pragma unroll
        for (int ks2 = 0; ks2 < 8; ks2++) {
            float a0 = Ps[pq * LDPK + ks2 * 8 + tg];
            float a1 = Ps[(pq + 8) * LDPK + ks2 * 8 + tg];
            float a2 = Ps[pq * LDPK + ks2 * 8 + tg + 4];
            float a3 = Ps[(pq + 8) * LDPK + ks2 * 8 + tg + 4];
            uint32_t h0 = f2tf(a0), h1 = f2tf(a1), h2 = f2tf(a2), h3 = f2tf(a3);
            uint32_t e0 = f2tf(a0 - __uint_as_float(h0));
            uint32_t e1 = f2tf(a1 - __uint_as_float(h1));
            uint32_t e2 = f2tf(a2 - __uint_as_float(h2));
            uint32_t e3 = f2tf(a3 - __uint_as_float(h3));
            #pragma unroll
            for (int ni = 0; ni < 16; ni++) {
                uint32_t b0 = *(const uint32_t*)&Vb[(ks2 * 8 + tg) * LDVV + ni * 8 + g];
                uint32_t b1 = *(const uint32_t*)&Vb[(ks2 * 8 + tg + 4) * LDVV + ni * 8 + g];
                mma_tf32(oacc[ni], h0, h1, h2, h3, b0, b1);
                mma_tf32(oacc[ni], e0, e1, e2, e3, b0, b1);
            }
        }
    }

    // ---- epilogue: O / l -> g_attn fp32 ----
    const float il0 = 1.0f / l0;
    const float il1 = 1.0f / l1;
    const size_t row0 = rowbase + qbase + w * 16 + g;
    #pragma unroll
    for (int ni = 0; ni < 16; ni++) {
        const int col = hoff + ni * 8 + 2 * tg;
        *(float2*)&g_attn[row0 * DD + col] =
            make_float2(oacc[ni][0] * il0, oacc[ni][1] * il0);
        *(float2*)&g_attn[(row0 + 8) * DD + col] =
            make_float2(oacc[ni][2] * il1, oacc[ni][3] * il1);
    }
}

// ---------------- launch ----------------
extern "C" void kernel_launch(void* const* d_in, const int* in_sizes, int n_in,
                              void* d_out, int out_size)
{
    const float* x    = (const float*)d_in[0];
    const float* Wkqv = (const float*)d_in[1];
    const float* bkqv = (const float*)d_in[2];
    const float* Wo   = (const float*)d_in[3];
    const float* bo   = (const float*)d_in[4];
    float* out = (float*)d_out;

    float *kqv, *attn, *xp, *wkp, *wop, *ap, *inv, *ct, *st;
    cudaGetSymbolAddress((void**)&kqv, g_kqv);
    cudaGetSymbolAddress((void**)&attn, g_attn);
    cudaGetSymbolAddress((void**)&xp,  g_xp);
    cudaGetSymbolAddress((void**)&wkp, g_wkp);
    cudaGetSymbolAddress((void**)&wop, g_wop);
    cudaGetSymbolAddress((void**)&ap,  g_ap);
    cudaGetSymbolAddress((void**)&inv, g_inv);
    cudaGetSymbolAddress((void**)&ct,  g_cos);
    cudaGetSymbolAddress((void**)&st,  g_sin);

    cudaFuncSetAttribute(gemm_packed_kernel, cudaFuncAttributeMaxDynamicSharedMemorySize, GEMM_SMEM);
    cudaFuncSetAttribute(attn_mma_kernel,    cudaFuncAttributeMaxDynamicSharedMemorySize, ATT_SMEM);

    // 0) rope tables + pack operands (tf32 rna rounding folded in)
    freq_kernel<<<1, 64>>>(inv);
    trig_kernel<<<(TT * 64) / 256, 256>>>(inv, ct, st);
    packA_kernel<<<dim3(DD / 64, MROWS / 32), 256>>>(x, (float4*)xp, MROWS, DD);
    packB_kernel<<<(DD / 4 * N3 + 255) / 256, 256>>>(Wkqv, (float4*)wkp, DD, N3);
    packB_kernel<<<(DD / 4 * DD + 255) / 256, 256>>>(Wo, (float4*)wop, DD, DD);

    // 1) kqv = x @ Wkqv + bkqv, fused rope + tf32 rounding
    gemm_packed_kernel<<<dim3(N3 / 128, MROWS / 128), 256, GEMM_SMEM>>>(
        (const float4*)xp, (const float4*)wkp, bkqv, kqv, MROWS, N3, DD, 1, ct, st);

    // 2) causal flash attention -> g_attn
    attn_mma_kernel<<<dim3(TT / 128, BB * HH), 256, ATT_SMEM>>>();

    // 3) pack attention output, then out = attn @ Wo + bo
    packA_kernel<<<dim3(DD / 64, MROWS / 32), 256>>>(attn, (float4*)ap, MROWS, DD);
    gemm_packed_kernel<<<dim3(DD / 128, MROWS / 128), 256, GEMM_SMEM>>>(
        (const float4*)ap, (const float4*)wop, bo, out, MROWS, DD, DD, 0, ct, st);
}